// round 13
// baseline (speedup 1.0000x reference)
#include <cuda_runtime.h>
#include <cstdint>

#define HDIM 768
#define NGRAPH 256
#define C3H (3 * HDIM)
#define SLOT (NGRAPH * HDIM)

__device__ float g_pooled[NGRAPH * C3H];   // [B, 3H]: nodes | edges | lang
__device__ float g_mid[NGRAPH * HDIM];     // pre-relu mid accumulator (bias-init)
__device__ float g_mid2[NGRAPH * HDIM];    // pre-relu mid2 accumulator (bias-init)

// End-of-call (and module-load) invariant: pooled node/edge cols are ZERO.
__global__ void pooled_zero_kernel() {
    int total = NGRAPH * 2 * HDIM;
    for (int i = blockIdx.x * blockDim.x + threadIdx.x; i < total;
         i += gridDim.x * blockDim.x) {
        int m = i / (2 * HDIM), c = i - m * (2 * HDIM);
        g_pooled[m * C3H + c] = 0.f;
    }
}

// Side stream start: pooled lang cols = b_lang; mid=b_mid; mid2=b_mid2; out=b_ans
__global__ void rest_init_kernel(const float* __restrict__ b_lang,
                                 const float* __restrict__ b_mid,
                                 const float* __restrict__ b_mid2,
                                 const float* __restrict__ b_ans,
                                 float* __restrict__ out, int A) {
    int total = SLOT + 2 * SLOT + NGRAPH * A;
    for (int i = blockIdx.x * blockDim.x + threadIdx.x; i < total;
         i += gridDim.x * blockDim.x) {
        if (i < SLOT) {
            int m = i / HDIM, h = i - m * HDIM;
            g_pooled[m * C3H + 2 * HDIM + h] = __ldg(b_lang + h);
        } else if (i < 2 * SLOT) {
            int j = i - SLOT;
            g_mid[j] = __ldg(b_mid + (j % HDIM));
        } else if (i < 3 * SLOT) {
            int j = i - 2 * SLOT;
            g_mid2[j] = __ldg(b_mid2 + (j % HDIM));
        } else {
            int j = i - 3 * SLOT;
            out[j] = __ldg(b_ans + (j % A));
        }
    }
}

// ---------------------------------------------------------------------------
// Segment sums (sorted ids). Register accumulation, atomic flush on change.
// Unroll x16 (MLP=16).
// ---------------------------------------------------------------------------
#define SEG_ROWS 256

__global__ __launch_bounds__(192) void seg_sum_full(
    const float* __restrict__ feat, const int* __restrict__ seg,
    int n, int col_off) {
    const int tid = threadIdx.x;  // 0..191
    long r0 = (long)blockIdx.x * SEG_ROWS;
    long r1 = r0 + SEG_ROWS;
    if (r1 > n) r1 = n;
    if (r0 >= r1) return;

    const float* base = feat + tid * 4;
    float4 acc = make_float4(0.f, 0.f, 0.f, 0.f);
    int cur = __ldg(seg + r0);

    long r = r0;
    while (r + 16 <= r1) {
        int slast = __ldg(seg + r + 15);
        float4 v[16];
        #pragma unroll
        for (int q = 0; q < 16; q++)
            v[q] = __ldcs(reinterpret_cast<const float4*>(base + (r + q) * HDIM));
        if (slast == cur) {
            #pragma unroll
            for (int q = 0; q < 16; q++) {
                acc.x += v[q].x; acc.y += v[q].y;
                acc.z += v[q].z; acc.w += v[q].w;
            }
        } else {
            #pragma unroll
            for (int q = 0; q < 16; q++) {
                int s = __ldg(seg + r + q);
                if (s != cur) {
                    float* o = g_pooled + (long)cur * C3H + col_off + tid * 4;
                    atomicAdd(o + 0, acc.x); atomicAdd(o + 1, acc.y);
                    atomicAdd(o + 2, acc.z); atomicAdd(o + 3, acc.w);
                    acc = make_float4(0.f, 0.f, 0.f, 0.f);
                    cur = s;
                }
                acc.x += v[q].x; acc.y += v[q].y;
                acc.z += v[q].z; acc.w += v[q].w;
            }
        }
        r += 16;
    }
    for (; r < r1; ++r) {
        int s = __ldg(seg + r);
        if (s != cur) {
            float* o = g_pooled + (long)cur * C3H + col_off + tid * 4;
            atomicAdd(o + 0, acc.x); atomicAdd(o + 1, acc.y);
            atomicAdd(o + 2, acc.z); atomicAdd(o + 3, acc.w);
            acc = make_float4(0.f, 0.f, 0.f, 0.f);
            cur = s;
        }
        float4 v = __ldcs(reinterpret_cast<const float4*>(base + r * HDIM));
        acc.x += v.x; acc.y += v.y; acc.z += v.z; acc.w += v.w;
    }
    {
        float* o = g_pooled + (long)cur * C3H + col_off + tid * 4;
        atomicAdd(o + 0, acc.x); atomicAdd(o + 1, acc.y);
        atomicAdd(o + 2, acc.z); atomicAdd(o + 3, acc.w);
    }
}

__global__ __launch_bounds__(192) void seg_sum_half(
    const float* __restrict__ feat, const int* __restrict__ seg,
    int n, int c0, int col_off) {
    const int tid = threadIdx.x;  // 0..191
    long r0 = (long)blockIdx.x * SEG_ROWS;
    long r1 = r0 + SEG_ROWS;
    if (r1 > n) r1 = n;
    if (r0 >= r1) return;

    const float* base = feat + c0 + tid * 2;
    float2 acc = make_float2(0.f, 0.f);
    int cur = __ldg(seg + r0);

    long r = r0;
    while (r + 16 <= r1) {
        int slast = __ldg(seg + r + 15);
        float2 v[16];
        #pragma unroll
        for (int q = 0; q < 16; q++)
            v[q] = __ldcs(reinterpret_cast<const float2*>(base + (r + q) * HDIM));
        if (slast == cur) {
            #pragma unroll
            for (int q = 0; q < 16; q++) { acc.x += v[q].x; acc.y += v[q].y; }
        } else {
            #pragma unroll
            for (int q = 0; q < 16; q++) {
                int s = __ldg(seg + r + q);
                if (s != cur) {
                    float* o = g_pooled + (long)cur * C3H + col_off + tid * 2;
                    atomicAdd(o + 0, acc.x); atomicAdd(o + 1, acc.y);
                    acc = make_float2(0.f, 0.f);
                    cur = s;
                }
                acc.x += v[q].x; acc.y += v[q].y;
            }
        }
        r += 16;
    }
    for (; r < r1; ++r) {
        int s = __ldg(seg + r);
        if (s != cur) {
            float* o = g_pooled + (long)cur * C3H + col_off + tid * 2;
            atomicAdd(o + 0, acc.x); atomicAdd(o + 1, acc.y);
            acc = make_float2(0.f, 0.f);
            cur = s;
        }
        float2 v = __ldcs(reinterpret_cast<const float2*>(base + r * HDIM));
        acc.x += v.x; acc.y += v.y;
    }
    {
        float* o = g_pooled + (long)cur * C3H + col_off + tid * 2;
        atomicAdd(o + 0, acc.x); atomicAdd(o + 1, acc.y);
    }
}

// ---------------------------------------------------------------------------
// TF32 tensor-core GEMM, 3xTF32, split-K, 3-stage cp.async pipeline,
// red.global epilogue into bias-initialized destination.
// ---------------------------------------------------------------------------
#define STAGES 3
#define AS_STRIDE 20
#define BS_STRIDE 136
#define AS_SZ (64 * AS_STRIDE)
#define BS_SZ (16 * BS_STRIDE)
#define STAGE_SZ (AS_SZ + BS_SZ)
#define GEMM_SMEM_BYTES (STAGES * STAGE_SZ * 4)   // 41472 B

__device__ __forceinline__ void cp16(float* dst, const float* src) {
    unsigned d = (unsigned)__cvta_generic_to_shared(dst);
    asm volatile("cp.async.cg.shared.global [%0], [%1], 16;" :: "r"(d), "l"(src));
}
__device__ __forceinline__ void cp4(float* dst, const float* src) {
    unsigned d = (unsigned)__cvta_generic_to_shared(dst);
    asm volatile("cp.async.ca.shared.global [%0], [%1], 4;" :: "r"(d), "l"(src));
}
#define CP_COMMIT() asm volatile("cp.async.commit_group;" ::: "memory")
#define CP_WAIT2()  asm volatile("cp.async.wait_group 2;" ::: "memory")

__device__ __forceinline__ void tf32split(float x, unsigned& hi, unsigned& lo) {
    unsigned h;
    asm("cvt.rna.tf32.f32 %0, %1;" : "=r"(h) : "f"(x));
    float hf = __uint_as_float(h);
    unsigned l;
    float d = x - hf;
    asm("cvt.rna.tf32.f32 %0, %1;" : "=r"(l) : "f"(d));
    hi = h; lo = l;
}

__device__ __forceinline__ void mma8(float* d, const unsigned* a, const unsigned* b) {
    asm("mma.sync.aligned.m16n8k8.row.col.f32.tf32.tf32.f32 "
        "{%0,%1,%2,%3},{%4,%5,%6,%7},{%8,%9},{%0,%1,%2,%3};"
        : "+f"(d[0]), "+f"(d[1]), "+f"(d[2]), "+f"(d[3])
        : "r"(a[0]), "r"(a[1]), "r"(a[2]), "r"(a[3]), "r"(b[0]), "r"(b[1]));
}

__device__ __forceinline__ void red2(float* p, float a, float b) {
    asm volatile("red.global.add.v2.f32 [%0], {%1, %2};"
                 :: "l"(p), "f"(a), "f"(b) : "memory");
}
__device__ __forceinline__ void red1(float* p, float a) {
    asm volatile("red.global.add.f32 [%0], %1;" :: "l"(p), "f"(a) : "memory");
}

template <bool RELU_A, bool BVEC, bool CVEC>
__global__ __launch_bounds__(256) void gemm_cp(
    const float* __restrict__ A, int lda,
    const float* __restrict__ W, int ldw,
    float* __restrict__ out, int ldc,
    int N, int Ksplit) {
    extern __shared__ float sm[];

    const int t = threadIdx.x;
    const int wid = t >> 5;
    const int lane = t & 31;
    const int wm = (wid & 1) * 32;
    const int wn = (wid >> 1) * 32;
    const int bm = blockIdx.y * 64;
    const int bn = blockIdx.x * 128;
    const int g = lane >> 2;
    const int tq = lane & 3;

    const int kbeg = blockIdx.z * Ksplit;
    const int ktiles = Ksplit / 16;

    const int ar = t & 63;
    const int aq = t >> 6;

#define AS(s,m,k) sm[(s)*STAGE_SZ + (m)*AS_STRIDE + (k)]
#define BS(s,k,n) sm[(s)*STAGE_SZ + AS_SZ + (k)*BS_STRIDE + (n)]

    auto issue = [&](int s, int tile) {
        int k0 = kbeg + tile * 16;
        cp16(&AS(s, ar, aq * 4), A + (long)(bm + ar) * lda + k0 + aq * 4);
        if (BVEC) {
            #pragma unroll
            for (int i = 0; i < 2; i++) {
                int idx = t + i * 256;
                int br = idx >> 5;
                int bc = (idx & 31) * 4;
                cp16(&BS(s, br, bc), W + (long)(k0 + br) * ldw + bn + bc);
            }
        } else {
            #pragma unroll
            for (int i = 0; i < 8; i++) {
                int idx = t + i * 256;
                int br = idx >> 7;
                int bc = idx & 127;
                int gn = bn + bc;
                if (gn < N) cp4(&BS(s, br, bc), W + (long)(k0 + br) * ldw + gn);
                else BS(s, br, bc) = 0.f;
            }
        }
    };

    float acc[2][4][4] = {};

    issue(0, 0); CP_COMMIT();
    if (ktiles > 1) issue(1, 1);
    CP_COMMIT();

    for (int i = 0; i < ktiles; i++) {
        if (i + 2 < ktiles) issue((i + 2) % STAGES, i + 2);
        CP_COMMIT();
        CP_WAIT2();
        __syncthreads();

        const int s = i % STAGES;
        #pragma unroll
        for (int kk = 0; kk < 16; kk += 8) {
            unsigned ah[2][4], al[2][4];
            #pragma unroll
            for (int mt = 0; mt < 2; mt++) {
                int row = wm + mt * 16 + g;
                float x0 = AS(s, row,     kk + tq);
                float x1 = AS(s, row + 8, kk + tq);
                float x2 = AS(s, row,     kk + tq + 4);
                float x3 = AS(s, row + 8, kk + tq + 4);
                if (RELU_A) {
                    x0 = fmaxf(x0, 0.f); x1 = fmaxf(x1, 0.f);
                    x2 = fmaxf(x2, 0.f); x3 = fmaxf(x3, 0.f);
                }
                tf32split(x0, ah[mt][0], al[mt][0]);
                tf32split(x1, ah[mt][1], al[mt][1]);
                tf32split(x2, ah[mt][2], al[mt][2]);
                tf32split(x3, ah[mt][3], al[mt][3]);
            }
            unsigned bh[4][2], bl[4][2];
            #pragma unroll
            for (int nt = 0; nt < 4; nt++) {
                int col = wn + nt * 8 + g;
                tf32split(BS(s, kk + tq,     col), bh[nt][0], bl[nt][0]);
                tf32split(BS(s, kk + tq + 4, col), bh[nt][1], bl[nt][1]);
            }
            #pragma unroll
            for (int mt = 0; mt < 2; mt++) {
                #pragma unroll
                for (int nt = 0; nt < 4; nt++) {
                    mma8(acc[mt][nt], ah[mt], bl[nt]);
                    mma8(acc[mt][nt], al[mt], bh[nt]);
                    mma8(acc[mt][nt], ah[mt], bh[nt]);
                }
            }
        }
        __syncthreads();
    }

    #pragma unroll
    for (int mt = 0; mt < 2; mt++) {
        int row = bm + wm + mt * 16 + g;
        #pragma unroll
        for (int nt = 0; nt < 4; nt++) {
            int col = bn + wn + nt * 8 + tq * 2;
            float* p0 = out + (long)row * ldc + col;
            float* p1 = out + (long)(row + 8) * ldc + col;
            if (CVEC) {
                if (col + 1 < N) {
                    red2(p0, acc[mt][nt][0], acc[mt][nt][1]);
                    red2(p1, acc[mt][nt][2], acc[mt][nt][3]);
                } else if (col < N) {
                    red1(p0, acc[mt][nt][0]);
                    red1(p1, acc[mt][nt][2]);
                }
            } else {
                if (col < N)     { red1(p0, acc[mt][nt][0]); red1(p1, acc[mt][nt][2]); }
                if (col + 1 < N) { red1(p0 + 1, acc[mt][nt][1]); red1(p1 + 1, acc[mt][nt][3]); }
            }
        }
    }
#undef AS
#undef BS
}

// ---------------------------------------------------------------------------

extern "C" void kernel_launch(void* const* d_in, const int* in_sizes, int n_in,
                              void* d_out, int out_size) {
    const float* node_feat = (const float*)d_in[0];
    const float* edge_feat = (const float*)d_in[1];
    const float* qemb      = (const float*)d_in[2];
    const int*   node_seg  = (const int*)d_in[3];
    const int*   edge_seg  = (const int*)d_in[4];
    const float* W_lang = (const float*)d_in[5];
    const float* b_lang = (const float*)d_in[6];
    const float* W_mid  = (const float*)d_in[7];
    const float* b_mid  = (const float*)d_in[8];
    const float* W_mid2 = (const float*)d_in[9];
    const float* b_mid2 = (const float*)d_in[10];
    const float* W_ans  = (const float*)d_in[11];
    const float* b_ans  = (const float*)d_in[12];

    const int N = in_sizes[3];
    const int E = in_sizes[4];
    const int A = in_sizes[12];   // 3129

    float *pooled, *mid, *mid2;
    cudaGetSymbolAddress((void**)&pooled, g_pooled);
    cudaGetSymbolAddress((void**)&mid, g_mid);
    cudaGetSymbolAddress((void**)&mid2, g_mid2);

    static cudaStream_t s1 = nullptr, s2 = nullptr, s3 = nullptr;
    static cudaEvent_t evStart, evInit, evN, evE1, evMN, evML, evME1, evEH2,
                       evMidDone, evAnsB, evPZ;
    if (!s1) {
        cudaStreamCreateWithFlags(&s1, cudaStreamNonBlocking);
        cudaStreamCreateWithFlags(&s2, cudaStreamNonBlocking);
        cudaStreamCreateWithFlags(&s3, cudaStreamNonBlocking);
        cudaEventCreateWithFlags(&evStart, cudaEventDisableTiming);
        cudaEventCreateWithFlags(&evInit, cudaEventDisableTiming);
        cudaEventCreateWithFlags(&evN, cudaEventDisableTiming);
        cudaEventCreateWithFlags(&evE1, cudaEventDisableTiming);
        cudaEventCreateWithFlags(&evMN, cudaEventDisableTiming);
        cudaEventCreateWithFlags(&evML, cudaEventDisableTiming);
        cudaEventCreateWithFlags(&evME1, cudaEventDisableTiming);
        cudaEventCreateWithFlags(&evEH2, cudaEventDisableTiming);
        cudaEventCreateWithFlags(&evMidDone, cudaEventDisableTiming);
        cudaEventCreateWithFlags(&evAnsB, cudaEventDisableTiming);
        cudaEventCreateWithFlags(&evPZ, cudaEventDisableTiming);
    }

    // Fork side streams from the capture stream (capture-legal).
    cudaEventRecord(evStart, 0);
    cudaStreamWaitEvent(s1, evStart, 0);

    // s1: all bias inits (pooled lang cols, mid, mid2, d_out). Off critical path.
    rest_init_kernel<<<784, 256, 0, s1>>>(b_lang, b_mid, b_mid2, b_ans,
                                          (float*)d_out, A);
    cudaEventRecord(evInit, s1);

    // s1: lang chain (in-order after init; overlaps node seg-sum)
    gemm_cp<false, true, true><<<dim3(6, 4, 12), 256, GEMM_SMEM_BYTES, s1>>>(
        qemb, HDIM, W_lang, HDIM, pooled + 2 * HDIM, C3H, HDIM, 64);
    gemm_cp<false, true, true><<<dim3(6, 4, 12), 256, GEMM_SMEM_BYTES, s1>>>(
        pooled + 2 * HDIM, C3H, W_mid + 2 * HDIM * HDIM, HDIM, mid, HDIM, HDIM, 64);
    cudaEventRecord(evML, s1);

    // s0: node seg-sum IMMEDIATELY (pooled node/edge cols are zero by the
    // end-of-call invariant; module-load zeros cover the very first call).
    seg_sum_full<<<(N + SEG_ROWS - 1) / SEG_ROWS, 192>>>(node_feat, node_seg, N, 0);
    cudaEventRecord(evN, 0);

    // s0: edge seg-sum, column halves
    seg_sum_half<<<(E + SEG_ROWS - 1) / SEG_ROWS, 192>>>(edge_feat, edge_seg, E, 0, HDIM);
    cudaEventRecord(evE1, 0);
    seg_sum_half<<<(E + SEG_ROWS - 1) / SEG_ROWS, 192>>>(edge_feat, edge_seg, E, 384, HDIM + 384);

    // s2: mid += nodes @ W_mid[0:768]   (overlaps edge seg-sums)
    cudaStreamWaitEvent(s2, evN, 0);
    cudaStreamWaitEvent(s2, evInit, 0);
    gemm_cp<false, true, true><<<dim3(6, 4, 12), 256, GEMM_SMEM_BYTES, s2>>>(
        pooled, C3H, W_mid, HDIM, mid, HDIM, HDIM, 64);
    cudaEventRecord(evMN, s2);

    // s3: mid += edges[:, :384] @ W_mid[768:1152]  (overlaps edge half 2)
    cudaStreamWaitEvent(s3, evE1, 0);
    cudaStreamWaitEvent(s3, evInit, 0);
    gemm_cp<false, true, true><<<dim3(6, 4, 6), 256, GEMM_SMEM_BYTES, s3>>>(
        pooled + HDIM, C3H, W_mid + HDIM * HDIM, HDIM, mid, HDIM, HDIM, 64);
    cudaEventRecord(evME1, s3);

    // s0: mid += edges[:, 384:768] @ W_mid[1152:1536]
    cudaStreamWaitEvent(0, evInit, 0);
    gemm_cp<false, true, true><<<dim3(6, 4, 6), 256, GEMM_SMEM_BYTES>>>(
        pooled + HDIM + 384, C3H, W_mid + (HDIM + 384) * (long)HDIM, HDIM,
        mid, HDIM, HDIM, 64);
    cudaEventRecord(evEH2, 0);

    // join mid on s0
    cudaStreamWaitEvent(0, evMN, 0);
    cudaStreamWaitEvent(0, evML, 0);
    cudaStreamWaitEvent(0, evME1, 0);
    cudaEventRecord(evMidDone, 0);

    // s1: end-of-call pooled zero (after all pooled readers; overlaps tail)
    cudaStreamWaitEvent(s1, evMN, 0);
    cudaStreamWaitEvent(s1, evME1, 0);
    cudaStreamWaitEvent(s1, evEH2, 0);
    pooled_zero_kernel<<<384, 256, 0, s1>>>();
    cudaEventRecord(evPZ, s1);

    // s0: mid2a = relu(mid) @ W_mid2[:, 0:384]
    gemm_cp<true, true, true><<<dim3(3, 4, 12), 256, GEMM_SMEM_BYTES>>>(
        mid, HDIM, W_mid2, HDIM, mid2, HDIM, 384, 64);

    // s2: mid2b = relu(mid) @ W_mid2[:, 384:768]
    cudaStreamWaitEvent(s2, evMidDone, 0);
    gemm_cp<true, true, true><<<dim3(3, 4, 12), 256, GEMM_SMEM_BYTES, s2>>>(
        mid, HDIM, W_mid2 + 384, HDIM, mid2 + 384, HDIM, 384, 64);

    // s0: ansA: d_out += relu(mid2[:, 0:384]) @ W_ans[0:384, :]
    gemm_cp<true, false, false><<<dim3(25, 4, 2), 256, GEMM_SMEM_BYTES>>>(
        mid2, HDIM, W_ans, A, (float*)d_out, A, A, 192);

    // s2: ansB: d_out += relu(mid2[:, 384:768]) @ W_ans[384:768, :]
    gemm_cp<true, false, false><<<dim3(25, 4, 2), 256, GEMM_SMEM_BYTES, s2>>>(
        mid2 + 384, HDIM, W_ans + 384 * (long)A, A, (float*)d_out, A, A, 192);
    cudaEventRecord(evAnsB, s2);

    // s0: final join — ALL side streams must terminate in the capture stream.
    cudaStreamWaitEvent(0, evAnsB, 0);
    cudaStreamWaitEvent(0, evPZ, 0);
}

// round 14
// speedup vs baseline: 1.0197x; 1.0197x over previous
#include <cuda_runtime.h>
#include <cstdint>

#define HDIM 768
#define NGRAPH 256
#define C3H (3 * HDIM)
#define SLOT (NGRAPH * HDIM)

__device__ float g_pooled[NGRAPH * C3H];   // [B, 3H]: nodes | edges | lang
__device__ float g_mid[NGRAPH * HDIM];     // pre-relu mid accumulator (bias-init)
__device__ float g_mid2[NGRAPH * HDIM];    // pre-relu mid2 accumulator (bias-init)
__device__ float g_sink;

// End-of-call (and module-load) invariant: pooled node/edge cols are ZERO.
__global__ void pooled_zero_kernel() {
    int total = NGRAPH * 2 * HDIM;
    for (int i = blockIdx.x * blockDim.x + threadIdx.x; i < total;
         i += gridDim.x * blockDim.x) {
        int m = i / (2 * HDIM), c = i - m * (2 * HDIM);
        g_pooled[m * C3H + c] = 0.f;
    }
}

// Side stream start: pooled lang cols = b_lang; mid=b_mid; mid2=b_mid2; out=b_ans
__global__ void rest_init_kernel(const float* __restrict__ b_lang,
                                 const float* __restrict__ b_mid,
                                 const float* __restrict__ b_mid2,
                                 const float* __restrict__ b_ans,
                                 float* __restrict__ out, int A) {
    int total = SLOT + 2 * SLOT + NGRAPH * A;
    for (int i = blockIdx.x * blockDim.x + threadIdx.x; i < total;
         i += gridDim.x * blockDim.x) {
        if (i < SLOT) {
            int m = i / HDIM, h = i - m * HDIM;
            g_pooled[m * C3H + 2 * HDIM + h] = __ldg(b_lang + h);
        } else if (i < 2 * SLOT) {
            int j = i - SLOT;
            g_mid[j] = __ldg(b_mid + (j % HDIM));
        } else if (i < 3 * SLOT) {
            int j = i - 2 * SLOT;
            g_mid2[j] = __ldg(b_mid2 + (j % HDIM));
        } else {
            int j = i - 3 * SLOT;
            out[j] = __ldg(b_ans + (j % A));
        }
    }
}

// Warm W_mid2 + W_ans into L2 (one float per 32B sector). Runs under node seg.
__global__ void prefetch_kernel(const float* __restrict__ w1, long n1,
                                const float* __restrict__ w2, long n2) {
    float s = 0.f;
    long i0 = ((long)blockIdx.x * blockDim.x + threadIdx.x) * 8;
    long stride = (long)gridDim.x * blockDim.x * 8;
    for (long i = i0; i < n1; i += stride) s += __ldg(w1 + i);
    for (long i = i0; i < n2; i += stride) s += __ldg(w2 + i);
    if (s == 1.2345e38f) g_sink = s;   // never true; defeats DCE
}

// ---------------------------------------------------------------------------
// Segment sums (sorted ids). Register accumulation, atomic flush on change.
// Unroll x16 (MLP=16).
// ---------------------------------------------------------------------------
#define SEG_ROWS 256

__global__ __launch_bounds__(192) void seg_sum_full(
    const float* __restrict__ feat, const int* __restrict__ seg,
    int n, int col_off) {
    const int tid = threadIdx.x;  // 0..191
    long r0 = (long)blockIdx.x * SEG_ROWS;
    long r1 = r0 + SEG_ROWS;
    if (r1 > n) r1 = n;
    if (r0 >= r1) return;

    const float* base = feat + tid * 4;
    float4 acc = make_float4(0.f, 0.f, 0.f, 0.f);
    int cur = __ldg(seg + r0);

    long r = r0;
    while (r + 16 <= r1) {
        int slast = __ldg(seg + r + 15);
        float4 v[16];
        #pragma unroll
        for (int q = 0; q < 16; q++)
            v[q] = __ldcs(reinterpret_cast<const float4*>(base + (r + q) * HDIM));
        if (slast == cur) {
            #pragma unroll
            for (int q = 0; q < 16; q++) {
                acc.x += v[q].x; acc.y += v[q].y;
                acc.z += v[q].z; acc.w += v[q].w;
            }
        } else {
            #pragma unroll
            for (int q = 0; q < 16; q++) {
                int s = __ldg(seg + r + q);
                if (s != cur) {
                    float* o = g_pooled + (long)cur * C3H + col_off + tid * 4;
                    atomicAdd(o + 0, acc.x); atomicAdd(o + 1, acc.y);
                    atomicAdd(o + 2, acc.z); atomicAdd(o + 3, acc.w);
                    acc = make_float4(0.f, 0.f, 0.f, 0.f);
                    cur = s;
                }
                acc.x += v[q].x; acc.y += v[q].y;
                acc.z += v[q].z; acc.w += v[q].w;
            }
        }
        r += 16;
    }
    for (; r < r1; ++r) {
        int s = __ldg(seg + r);
        if (s != cur) {
            float* o = g_pooled + (long)cur * C3H + col_off + tid * 4;
            atomicAdd(o + 0, acc.x); atomicAdd(o + 1, acc.y);
            atomicAdd(o + 2, acc.z); atomicAdd(o + 3, acc.w);
            acc = make_float4(0.f, 0.f, 0.f, 0.f);
            cur = s;
        }
        float4 v = __ldcs(reinterpret_cast<const float4*>(base + r * HDIM));
        acc.x += v.x; acc.y += v.y; acc.z += v.z; acc.w += v.w;
    }
    {
        float* o = g_pooled + (long)cur * C3H + col_off + tid * 4;
        atomicAdd(o + 0, acc.x); atomicAdd(o + 1, acc.y);
        atomicAdd(o + 2, acc.z); atomicAdd(o + 3, acc.w);
    }
}

__global__ __launch_bounds__(192) void seg_sum_half(
    const float* __restrict__ feat, const int* __restrict__ seg,
    int n, int c0, int col_off) {
    const int tid = threadIdx.x;  // 0..191
    long r0 = (long)blockIdx.x * SEG_ROWS;
    long r1 = r0 + SEG_ROWS;
    if (r1 > n) r1 = n;
    if (r0 >= r1) return;

    const float* base = feat + c0 + tid * 2;
    float2 acc = make_float2(0.f, 0.f);
    int cur = __ldg(seg + r0);

    long r = r0;
    while (r + 16 <= r1) {
        int slast = __ldg(seg + r + 15);
        float2 v[16];
        #pragma unroll
        for (int q = 0; q < 16; q++)
            v[q] = __ldcs(reinterpret_cast<const float2*>(base + (r + q) * HDIM));
        if (slast == cur) {
            #pragma unroll
            for (int q = 0; q < 16; q++) { acc.x += v[q].x; acc.y += v[q].y; }
        } else {
            #pragma unroll
            for (int q = 0; q < 16; q++) {
                int s = __ldg(seg + r + q);
                if (s != cur) {
                    float* o = g_pooled + (long)cur * C3H + col_off + tid * 2;
                    atomicAdd(o + 0, acc.x); atomicAdd(o + 1, acc.y);
                    acc = make_float2(0.f, 0.f);
                    cur = s;
                }
                acc.x += v[q].x; acc.y += v[q].y;
            }
        }
        r += 16;
    }
    for (; r < r1; ++r) {
        int s = __ldg(seg + r);
        if (s != cur) {
            float* o = g_pooled + (long)cur * C3H + col_off + tid * 2;
            atomicAdd(o + 0, acc.x); atomicAdd(o + 1, acc.y);
            acc = make_float2(0.f, 0.f);
            cur = s;
        }
        float2 v = __ldcs(reinterpret_cast<const float2*>(base + r * HDIM));
        acc.x += v.x; acc.y += v.y;
    }
    {
        float* o = g_pooled + (long)cur * C3H + col_off + tid * 2;
        atomicAdd(o + 0, acc.x); atomicAdd(o + 1, acc.y);
    }
}

// ---------------------------------------------------------------------------
// TF32 tensor-core GEMM, 3xTF32, split-K, 3-stage cp.async pipeline,
// red.global epilogue into bias-initialized destination.
// ---------------------------------------------------------------------------
#define STAGES 3
#define AS_STRIDE 20
#define BS_STRIDE 136
#define AS_SZ (64 * AS_STRIDE)
#define BS_SZ (16 * BS_STRIDE)
#define STAGE_SZ (AS_SZ + BS_SZ)
#define GEMM_SMEM_BYTES (STAGES * STAGE_SZ * 4)   // 41472 B

__device__ __forceinline__ void cp16(float* dst, const float* src) {
    unsigned d = (unsigned)__cvta_generic_to_shared(dst);
    asm volatile("cp.async.cg.shared.global [%0], [%1], 16;" :: "r"(d), "l"(src));
}
__device__ __forceinline__ void cp4(float* dst, const float* src) {
    unsigned d = (unsigned)__cvta_generic_to_shared(dst);
    asm volatile("cp.async.ca.shared.global [%0], [%1], 4;" :: "r"(d), "l"(src));
}
#define CP_COMMIT() asm volatile("cp.async.commit_group;" ::: "memory")
#define CP_WAIT2()  asm volatile("cp.async.wait_group 2;" ::: "memory")

__device__ __forceinline__ void tf32split(float x, unsigned& hi, unsigned& lo) {
    unsigned h;
    asm("cvt.rna.tf32.f32 %0, %1;" : "=r"(h) : "f"(x));
    float hf = __uint_as_float(h);
    unsigned l;
    float d = x - hf;
    asm("cvt.rna.tf32.f32 %0, %1;" : "=r"(l) : "f"(d));
    hi = h; lo = l;
}

__device__ __forceinline__ void mma8(float* d, const unsigned* a, const unsigned* b) {
    asm("mma.sync.aligned.m16n8k8.row.col.f32.tf32.tf32.f32 "
        "{%0,%1,%2,%3},{%4,%5,%6,%7},{%8,%9},{%0,%1,%2,%3};"
        : "+f"(d[0]), "+f"(d[1]), "+f"(d[2]), "+f"(d[3])
        : "r"(a[0]), "r"(a[1]), "r"(a[2]), "r"(a[3]), "r"(b[0]), "r"(b[1]));
}

__device__ __forceinline__ void red2(float* p, float a, float b) {
    asm volatile("red.global.add.v2.f32 [%0], {%1, %2};"
                 :: "l"(p), "f"(a), "f"(b) : "memory");
}
__device__ __forceinline__ void red1(float* p, float a) {
    asm volatile("red.global.add.f32 [%0], %1;" :: "l"(p), "f"(a) : "memory");
}

template <bool RELU_A, bool BVEC, bool CVEC>
__global__ __launch_bounds__(256) void gemm_cp(
    const float* __restrict__ A, int lda,
    const float* __restrict__ W, int ldw,
    float* __restrict__ out, int ldc,
    int N, int Ksplit) {
    extern __shared__ float sm[];

    const int t = threadIdx.x;
    const int wid = t >> 5;
    const int lane = t & 31;
    const int wm = (wid & 1) * 32;
    const int wn = (wid >> 1) * 32;
    const int bm = blockIdx.y * 64;
    const int bn = blockIdx.x * 128;
    const int g = lane >> 2;
    const int tq = lane & 3;

    const int kbeg = blockIdx.z * Ksplit;
    const int ktiles = Ksplit / 16;

    const int ar = t & 63;
    const int aq = t >> 6;

#define AS(s,m,k) sm[(s)*STAGE_SZ + (m)*AS_STRIDE + (k)]
#define BS(s,k,n) sm[(s)*STAGE_SZ + AS_SZ + (k)*BS_STRIDE + (n)]

    auto issue = [&](int s, int tile) {
        int k0 = kbeg + tile * 16;
        cp16(&AS(s, ar, aq * 4), A + (long)(bm + ar) * lda + k0 + aq * 4);
        if (BVEC) {
            #pragma unroll
            for (int i = 0; i < 2; i++) {
                int idx = t + i * 256;
                int br = idx >> 5;
                int bc = (idx & 31) * 4;
                cp16(&BS(s, br, bc), W + (long)(k0 + br) * ldw + bn + bc);
            }
        } else {
            #pragma unroll
            for (int i = 0; i < 8; i++) {
                int idx = t + i * 256;
                int br = idx >> 7;
                int bc = idx & 127;
                int gn = bn + bc;
                if (gn < N) cp4(&BS(s, br, bc), W + (long)(k0 + br) * ldw + gn);
                else BS(s, br, bc) = 0.f;
            }
        }
    };

    float acc[2][4][4] = {};

    issue(0, 0); CP_COMMIT();
    if (ktiles > 1) issue(1, 1);
    CP_COMMIT();

    for (int i = 0; i < ktiles; i++) {
        if (i + 2 < ktiles) issue((i + 2) % STAGES, i + 2);
        CP_COMMIT();
        CP_WAIT2();
        __syncthreads();

        const int s = i % STAGES;
        #pragma unroll
        for (int kk = 0; kk < 16; kk += 8) {
            unsigned ah[2][4], al[2][4];
            #pragma unroll
            for (int mt = 0; mt < 2; mt++) {
                int row = wm + mt * 16 + g;
                float x0 = AS(s, row,     kk + tq);
                float x1 = AS(s, row + 8, kk + tq);
                float x2 = AS(s, row,     kk + tq + 4);
                float x3 = AS(s, row + 8, kk + tq + 4);
                if (RELU_A) {
                    x0 = fmaxf(x0, 0.f); x1 = fmaxf(x1, 0.f);
                    x2 = fmaxf(x2, 0.f); x3 = fmaxf(x3, 0.f);
                }
                tf32split(x0, ah[mt][0], al[mt][0]);
                tf32split(x1, ah[mt][1], al[mt][1]);
                tf32split(x2, ah[mt][2], al[mt][2]);
                tf32split(x3, ah[mt][3], al[mt][3]);
            }
            unsigned bh[4][2], bl[4][2];
            #pragma unroll
            for (int nt = 0; nt < 4; nt++) {
                int col = wn + nt * 8 + g;
                tf32split(BS(s, kk + tq,     col), bh[nt][0], bl[nt][0]);
                tf32split(BS(s, kk + tq + 4, col), bh[nt][1], bl[nt][1]);
            }
            #pragma unroll
            for (int mt = 0; mt < 2; mt++) {
                #pragma unroll
                for (int nt = 0; nt < 4; nt++) {
                    mma8(acc[mt][nt], ah[mt], bl[nt]);
                    mma8(acc[mt][nt], al[mt], bh[nt]);
                    mma8(acc[mt][nt], ah[mt], bh[nt]);
                }
            }
        }
        __syncthreads();
    }

    #pragma unroll
    for (int mt = 0; mt < 2; mt++) {
        int row = bm + wm + mt * 16 + g;
        #pragma unroll
        for (int nt = 0; nt < 4; nt++) {
            int col = bn + wn + nt * 8 + tq * 2;
            float* p0 = out + (long)row * ldc + col;
            float* p1 = out + (long)(row + 8) * ldc + col;
            if (CVEC) {
                if (col + 1 < N) {
                    red2(p0, acc[mt][nt][0], acc[mt][nt][1]);
                    red2(p1, acc[mt][nt][2], acc[mt][nt][3]);
                } else if (col < N) {
                    red1(p0, acc[mt][nt][0]);
                    red1(p1, acc[mt][nt][2]);
                }
            } else {
                if (col < N)     { red1(p0, acc[mt][nt][0]); red1(p1, acc[mt][nt][2]); }
                if (col + 1 < N) { red1(p0 + 1, acc[mt][nt][1]); red1(p1 + 1, acc[mt][nt][3]); }
            }
        }
    }
#undef AS
#undef BS
}

// ---------------------------------------------------------------------------

extern "C" void kernel_launch(void* const* d_in, const int* in_sizes, int n_in,
                              void* d_out, int out_size) {
    const float* node_feat = (const float*)d_in[0];
    const float* edge_feat = (const float*)d_in[1];
    const float* qemb      = (const float*)d_in[2];
    const int*   node_seg  = (const int*)d_in[3];
    const int*   edge_seg  = (const int*)d_in[4];
    const float* W_lang = (const float*)d_in[5];
    const float* b_lang = (const float*)d_in[6];
    const float* W_mid  = (const float*)d_in[7];
    const float* b_mid  = (const float*)d_in[8];
    const float* W_mid2 = (const float*)d_in[9];
    const float* b_mid2 = (const float*)d_in[10];
    const float* W_ans  = (const float*)d_in[11];
    const float* b_ans  = (const float*)d_in[12];

    const int N = in_sizes[3];
    const int E = in_sizes[4];
    const int A = in_sizes[12];   // 3129

    float *pooled, *mid, *mid2;
    cudaGetSymbolAddress((void**)&pooled, g_pooled);
    cudaGetSymbolAddress((void**)&mid, g_mid);
    cudaGetSymbolAddress((void**)&mid2, g_mid2);

    static cudaStream_t s1 = nullptr, s2 = nullptr, s3 = nullptr;
    static cudaEvent_t evStart, evInit, evN, evE1, evMN, evML, evME1, evEH2, evPZ;
    if (!s1) {
        cudaStreamCreateWithFlags(&s1, cudaStreamNonBlocking);
        cudaStreamCreateWithFlags(&s2, cudaStreamNonBlocking);
        cudaStreamCreateWithFlags(&s3, cudaStreamNonBlocking);
        cudaEventCreateWithFlags(&evStart, cudaEventDisableTiming);
        cudaEventCreateWithFlags(&evInit, cudaEventDisableTiming);
        cudaEventCreateWithFlags(&evN, cudaEventDisableTiming);
        cudaEventCreateWithFlags(&evE1, cudaEventDisableTiming);
        cudaEventCreateWithFlags(&evMN, cudaEventDisableTiming);
        cudaEventCreateWithFlags(&evML, cudaEventDisableTiming);
        cudaEventCreateWithFlags(&evME1, cudaEventDisableTiming);
        cudaEventCreateWithFlags(&evEH2, cudaEventDisableTiming);
        cudaEventCreateWithFlags(&evPZ, cudaEventDisableTiming);
    }

    // Fork side streams from the capture stream (capture-legal).
    cudaEventRecord(evStart, 0);
    cudaStreamWaitEvent(s1, evStart, 0);

    // s1: all bias inits (pooled lang cols, mid, mid2, d_out). Off critical path.
    rest_init_kernel<<<784, 256, 0, s1>>>(b_lang, b_mid, b_mid2, b_ans,
                                          (float*)d_out, A);
    cudaEventRecord(evInit, s1);

    // s1: lang chain (in-order after init; overlaps node seg-sum)
    gemm_cp<false, true, true><<<dim3(6, 4, 12), 256, GEMM_SMEM_BYTES, s1>>>(
        qemb, HDIM, W_lang, HDIM, pooled + 2 * HDIM, C3H, HDIM, 64);
    gemm_cp<false, true, true><<<dim3(6, 4, 12), 256, GEMM_SMEM_BYTES, s1>>>(
        pooled + 2 * HDIM, C3H, W_mid + 2 * HDIM * HDIM, HDIM, mid, HDIM, HDIM, 64);
    cudaEventRecord(evML, s1);

    // s1: warm tail weights (W_mid2, W_ans) into L2 while seg-sums stream
    prefetch_kernel<<<296, 256, 0, s1>>>(W_mid2, (long)HDIM * HDIM,
                                         W_ans, (long)HDIM * A);

    // s0: node seg-sum IMMEDIATELY (pooled node/edge cols zero by the
    // end-of-call invariant; module-load zeros cover the very first call).
    seg_sum_full<<<(N + SEG_ROWS - 1) / SEG_ROWS, 192>>>(node_feat, node_seg, N, 0);
    cudaEventRecord(evN, 0);

    // s0: edge seg-sum, column halves
    seg_sum_half<<<(E + SEG_ROWS - 1) / SEG_ROWS, 192>>>(edge_feat, edge_seg, E, 0, HDIM);
    cudaEventRecord(evE1, 0);
    seg_sum_half<<<(E + SEG_ROWS - 1) / SEG_ROWS, 192>>>(edge_feat, edge_seg, E, 384, HDIM + 384);

    // s2: mid += nodes @ W_mid[0:768]   (overlaps edge seg-sums)
    cudaStreamWaitEvent(s2, evN, 0);
    cudaStreamWaitEvent(s2, evInit, 0);
    gemm_cp<false, true, true><<<dim3(6, 4, 12), 256, GEMM_SMEM_BYTES, s2>>>(
        pooled, C3H, W_mid, HDIM, mid, HDIM, HDIM, 64);
    cudaEventRecord(evMN, s2);

    // s3: mid += edges[:, :384] @ W_mid[768:1152]  (overlaps edge half 2)
    cudaStreamWaitEvent(s3, evE1, 0);
    cudaStreamWaitEvent(s3, evInit, 0);
    gemm_cp<false, true, true><<<dim3(6, 4, 6), 256, GEMM_SMEM_BYTES, s3>>>(
        pooled + HDIM, C3H, W_mid + HDIM * HDIM, HDIM, mid, HDIM, HDIM, 64);
    cudaEventRecord(evME1, s3);

    // s0: mid += edges[:, 384:768] @ W_mid[1152:1536]
    cudaStreamWaitEvent(0, evInit, 0);
    gemm_cp<false, true, true><<<dim3(6, 4, 6), 256, GEMM_SMEM_BYTES>>>(
        pooled + HDIM + 384, C3H, W_mid + (HDIM + 384) * (long)HDIM, HDIM,
        mid, HDIM, HDIM, 64);
    cudaEventRecord(evEH2, 0);

    // join mid on s0
    cudaStreamWaitEvent(0, evMN, 0);
    cudaStreamWaitEvent(0, evML, 0);
    cudaStreamWaitEvent(0, evME1, 0);

    // s1: end-of-call pooled zero (after all pooled readers; overlaps tail)
    cudaStreamWaitEvent(s1, evMN, 0);
    cudaStreamWaitEvent(s1, evME1, 0);
    cudaStreamWaitEvent(s1, evEH2, 0);
    pooled_zero_kernel<<<384, 256, 0, s1>>>();
    cudaEventRecord(evPZ, s1);

    // s0: mid2 += relu(mid) @ W_mid2   (full width — best measured shape)
    gemm_cp<true, true, true><<<dim3(6, 4, 12), 256, GEMM_SMEM_BYTES>>>(
        mid, HDIM, W_mid2, HDIM, mid2, HDIM, HDIM, 64);

    // s0: d_out += relu(mid2) @ W_ans  (full width, z=3)
    gemm_cp<true, false, false><<<dim3(25, 4, 3), 256, GEMM_SMEM_BYTES>>>(
        mid2, HDIM, W_ans, A, (float*)d_out, A, A, 256);

    // final join — all side streams terminate in the capture stream.
    cudaStreamWaitEvent(0, evPZ, 0);
}